// round 11
// baseline (speedup 1.0000x reference)
#include <cuda_runtime.h>
#include <cuda_bf16.h>
#include <cstdint>

#define B_ 16
#define Q_ 2048
#define S_ 2048
#define D_ 128
#define NEG_INF __int_as_float(0xff800000)

#define SSPLIT 2                 // k_pv S-dimension split factor
#define SSEG   (S_ / SSPLIT)     // 1024 s per CTA

// byte-level SW128 swizzle (R4-verified)
#define SWZ(o) ((o) ^ (((o) >> 3) & 0x70))

__device__ int g_mask_mode;   // 0 = uint8, 1 = int32, 2 = float32

// ---------------------------------------------------------------------------
__global__ void k_probe_mask(const unsigned int* __restrict__ m)
{
    const int lane = threadIdx.x;
    bool i32 = true, f32 = true;
    for (int i = lane; i < 1024; i += 32) {
        unsigned int w = m[i];
        if (w > 1u) i32 = false;
        if (w != 0u && w != 0x3F800000u) f32 = false;
    }
    unsigned bi = __ballot_sync(0xffffffffu, i32);
    unsigned bf = __ballot_sync(0xffffffffu, f32);
    if (lane == 0) g_mask_mode = (bi == 0xffffffffu) ? 1 : ((bf == 0xffffffffu) ? 2 : 0);
}

// zero-init the out region (d_out is poisoned; k_pv accumulates atomically)
__global__ void k_zero_out(float4* __restrict__ O4)
{
    O4[blockIdx.x * 256 + threadIdx.x] = make_float4(0.f, 0.f, 0.f, 0.f);
}

// ---------------------------------------------------------------------------
__device__ __forceinline__ void split_pack(float x, float y, uint32_t& hi, uint32_t& lo)
{
    __nv_bfloat16 hx = __float2bfloat16_rn(x);
    __nv_bfloat16 hy = __float2bfloat16_rn(y);
    __nv_bfloat16 lx = __float2bfloat16_rn(x - __bfloat162float(hx));
    __nv_bfloat16 ly = __float2bfloat16_rn(y - __bfloat162float(hy));
    hi = (uint32_t)__bfloat16_as_ushort(hx) | ((uint32_t)__bfloat16_as_ushort(hy) << 16);
    lo = (uint32_t)__bfloat16_as_ushort(lx) | ((uint32_t)__bfloat16_as_ushort(ly) << 16);
}

__device__ __forceinline__ void split8(const float4& a, const float4& b, uint4& hi, uint4& lo)
{
    split_pack(a.x, a.y, hi.x, lo.x);
    split_pack(a.z, a.w, hi.y, lo.y);
    split_pack(b.x, b.y, hi.z, lo.z);
    split_pack(b.z, b.w, hi.w, lo.w);
}

__device__ __forceinline__ void mma16816(float (&c)[4], const uint32_t (&a)[4], const uint32_t* b)
{
    asm volatile(
        "mma.sync.aligned.m16n8k16.row.col.f32.bf16.bf16.f32 "
        "{%0,%1,%2,%3}, {%4,%5,%6,%7}, {%8,%9}, {%0,%1,%2,%3};\n"
        : "+f"(c[0]), "+f"(c[1]), "+f"(c[2]), "+f"(c[3])
        : "r"(a[0]), "r"(a[1]), "r"(a[2]), "r"(a[3]), "r"(b[0]), "r"(b[1]));
}

__device__ __forceinline__ void ldsm_x4(uint32_t (&r)[4], uint32_t addr)
{
    asm volatile("ldmatrix.sync.aligned.m8n8.x4.shared.b16 {%0,%1,%2,%3}, [%4];\n"
                 : "=r"(r[0]), "=r"(r[1]), "=r"(r[2]), "=r"(r[3]) : "r"(addr));
}

__device__ __forceinline__ uint32_t sptr(const void* p)
{
    return (uint32_t)__cvta_generic_to_shared(p);
}

// ---------------------------------------------------------------------------
// Kernel 1: scores = mask ? -inf : (Q K^T) * D^-0.5  -- R8-proven, unchanged.
// ---------------------------------------------------------------------------
__global__ __launch_bounds__(512, 1) void k_scores(
    const float* __restrict__ Qm, const float* __restrict__ Km,
    const void* __restrict__ mask, float* __restrict__ P)
{
    extern __shared__ __align__(128) uint8_t sm[];

    const int b  = blockIdx.z;
    const int q0 = blockIdx.y * 128;
    const int s0 = blockIdx.x * 128;
    const float* Qb = Qm + ((size_t)b * Q_ + q0) * D_;
    const float* Kb = Km + ((size_t)b * S_ + s0) * D_;

    const int tid  = threadIdx.x;
    const int lane = tid & 31;
    const int wid  = tid >> 5;
    const int g    = lane >> 2;
    const int tg   = lane & 3;
    const int mw   = wid >> 2;
    const int nw   = wid & 3;

    float acc[2][4][4];
#pragma unroll
    for (int i = 0; i < 2; i++)
#pragma unroll
        for (int j = 0; j < 4; j++)
#pragma unroll
            for (int k = 0; k < 4; k++) acc[i][j][k] = 0.f;

    const int r = tid >> 2;
    const int c = tid & 3;
    const uint32_t sts_off = SWZ((uint32_t)(r * 64 + c * 16));

    const uint32_t a_row[2] = { (uint32_t)(mw * 32 + 0  + (lane & 15)),
                                (uint32_t)(mw * 32 + 16 + (lane & 15)) };
    const uint32_t a_chq    = (uint32_t)(lane >> 4);
    const uint32_t b_row[2] = { (uint32_t)(nw * 32 + 0  + (lane & 7) + ((lane & 16) >> 1)),
                                (uint32_t)(nw * 32 + 16 + (lane & 7) + ((lane & 16) >> 1)) };
    const uint32_t b_chq    = (uint32_t)((lane >> 3) & 1);

    {
        float4 q0v = *(const float4*)(Qb + (size_t)r * D_ + c * 8);
        float4 q1v = *(const float4*)(Qb + (size_t)r * D_ + c * 8 + 4);
        float4 k0v = *(const float4*)(Kb + (size_t)r * D_ + c * 8);
        float4 k1v = *(const float4*)(Kb + (size_t)r * D_ + c * 8 + 4);
        uint4 h, l;
        split8(q0v, q1v, h, l);
        *(uint4*)(sm + sts_off)        = h;
        *(uint4*)(sm + 8192 + sts_off) = l;
        split8(k0v, k1v, h, l);
        *(uint4*)(sm + 16384 + sts_off) = h;
        *(uint4*)(sm + 24576 + sts_off) = l;
    }
    __syncthreads();

    for (int dc = 0; dc < D_; dc += 32) {
        const uint32_t cur = ((dc >> 5) & 1) * 32768u;
        const uint32_t nxt = cur ^ 32768u;
        const bool more = (dc + 32 < D_);

        float4 q0v, q1v, k0v, k1v;
        if (more) {
            q0v = *(const float4*)(Qb + (size_t)r * D_ + dc + 32 + c * 8);
            q1v = *(const float4*)(Qb + (size_t)r * D_ + dc + 32 + c * 8 + 4);
            k0v = *(const float4*)(Kb + (size_t)r * D_ + dc + 32 + c * 8);
            k1v = *(const float4*)(Kb + (size_t)r * D_ + dc + 32 + c * 8 + 4);
        }

#pragma unroll
        for (int ks = 0; ks < 2; ks++) {
            uint32_t ah[2][4], al[2][4];
#pragma unroll
            for (int mi = 0; mi < 2; mi++) {
                uint32_t off = cur + SWZ(a_row[mi] * 64 + (2 * ks + a_chq) * 16);
                ldsm_x4(ah[mi], sptr(sm) + off);
                ldsm_x4(al[mi], sptr(sm) + 8192 + off);
            }
            uint32_t bh[2][4], bl[2][4];
#pragma unroll
            for (int njp = 0; njp < 2; njp++) {
                uint32_t off = cur + SWZ(b_row[njp] * 64 + (2 * ks + b_chq) * 16);
                ldsm_x4(bh[njp], sptr(sm) + 16384 + off);
                ldsm_x4(bl[njp], sptr(sm) + 24576 + off);
            }
#pragma unroll
            for (int mi = 0; mi < 2; mi++)
#pragma unroll
                for (int njp = 0; njp < 2; njp++)
#pragma unroll
                    for (int j = 0; j < 2; j++) {
                        float (&cacc)[4] = acc[mi][njp * 2 + j];
                        mma16816(cacc, ah[mi], &bh[njp][2 * j]);
                        mma16816(cacc, ah[mi], &bl[njp][2 * j]);
                        mma16816(cacc, al[mi], &bh[njp][2 * j]);
                    }
        }

        if (more) {
            uint4 h, l;
            split8(q0v, q1v, h, l);
            *(uint4*)(sm + nxt + sts_off)        = h;
            *(uint4*)(sm + nxt + 8192 + sts_off) = l;
            split8(k0v, k1v, h, l);
            *(uint4*)(sm + nxt + 16384 + sts_off) = h;
            *(uint4*)(sm + nxt + 24576 + sts_off) = l;
        }
        __syncthreads();
    }

    const float scale = 0.08838834764831845f;  // 128^-0.5
    const int mm = g_mask_mode;
#pragma unroll
    for (int mi = 0; mi < 2; mi++) {
#pragma unroll
        for (int hh = 0; hh < 2; hh++) {
            const int q = q0 + mw * 32 + mi * 16 + hh * 8 + g;
            const size_t rowoff = ((size_t)b * Q_ + q) * (size_t)S_;
#pragma unroll
            for (int nj = 0; nj < 4; nj++) {
                const int s = s0 + nw * 32 + nj * 8 + tg * 2;
                const size_t off = rowoff + s;
                const float v0 = acc[mi][nj][hh * 2 + 0] * scale;
                const float v1 = acc[mi][nj][hh * 2 + 1] * scale;
                bool m0, m1;
                if (mm == 1) {
                    int2 w = *(const int2*)((const int*)mask + off);
                    m0 = w.x != 0; m1 = w.y != 0;
                } else if (mm == 2) {
                    float2 w = *(const float2*)((const float*)mask + off);
                    m0 = w.x != 0.f; m1 = w.y != 0.f;
                } else {
                    const unsigned char* mu = (const unsigned char*)mask + off;
                    m0 = mu[0] != 0; m1 = mu[1] != 0;
                }
                float2 o;
                o.x = m0 ? NEG_INF : v0;
                o.y = m1 ? NEG_INF : v1;
                *(float2*)(P + off) = o;
            }
        }
    }
}

// ---------------------------------------------------------------------------
// Kernel 2: in-place row softmax over S=2048. R8-proven, unchanged.
// ---------------------------------------------------------------------------
__global__ __launch_bounds__(256) void k_softmax(float* __restrict__ P)
{
    __shared__ float red[8];
    const size_t row = blockIdx.x;
    float* p = P + row * (size_t)S_;
    const int tid  = threadIdx.x;
    const int lane = tid & 31;
    const int wid  = tid >> 5;

    float4 v0 = ((const float4*)p)[tid];
    float4 v1 = ((const float4*)p)[tid + 256];

    float m = fmaxf(fmaxf(fmaxf(v0.x, v0.y), fmaxf(v0.z, v0.w)),
                    fmaxf(fmaxf(v1.x, v1.y), fmaxf(v1.z, v1.w)));
#pragma unroll
    for (int o = 16; o; o >>= 1) m = fmaxf(m, __shfl_xor_sync(0xffffffffu, m, o));
    if (lane == 0) red[wid] = m;
    __syncthreads();
    m = red[0];
#pragma unroll
    for (int w = 1; w < 8; w++) m = fmaxf(m, red[w]);
    __syncthreads();

    float e[8];
    e[0] = __expf(v0.x - m); e[1] = __expf(v0.y - m);
    e[2] = __expf(v0.z - m); e[3] = __expf(v0.w - m);
    e[4] = __expf(v1.x - m); e[5] = __expf(v1.y - m);
    e[6] = __expf(v1.z - m); e[7] = __expf(v1.w - m);
    float s = ((e[0] + e[1]) + (e[2] + e[3])) + ((e[4] + e[5]) + (e[6] + e[7]));
#pragma unroll
    for (int o = 16; o; o >>= 1) s += __shfl_xor_sync(0xffffffffu, s, o);
    if (lane == 0) red[wid] = s;
    __syncthreads();
    s = red[0];
#pragma unroll
    for (int w = 1; w < 8; w++) s += red[w];

    const float inv = 1.0f / s;
    v0.x = e[0] * inv; v0.y = e[1] * inv; v0.z = e[2] * inv; v0.w = e[3] * inv;
    v1.x = e[4] * inv; v1.y = e[5] * inv; v1.z = e[6] * inv; v1.w = e[7] * inv;
    ((float4*)p)[tid]       = v0;
    ((float4*)p)[tid + 256] = v1;
}

// ---------------------------------------------------------------------------
// Kernel 3: out += P_seg @ V_seg  (R8 mainloop; S split across blockIdx.z).
// CTA 128q x 128d x 1024s, 512 thr, double-buffered smem, REDG epilogue.
// ---------------------------------------------------------------------------
__global__ __launch_bounds__(512, 1) void k_pv(
    const float* __restrict__ P, const float* __restrict__ V,
    float* __restrict__ O)
{
    extern __shared__ __align__(128) uint8_t sm[];

    const int b   = blockIdx.y;
    const int q0  = blockIdx.x * 128;
    const int sc0 = blockIdx.z * SSEG;
    const float* Pb = P + ((size_t)b * Q_ + q0) * (size_t)S_;
    const float* Vb = V + (size_t)b * S_ * D_;

    const int tid  = threadIdx.x;
    const int lane = tid & 31;
    const int wid  = tid >> 5;
    const int g    = lane >> 2;
    const int tg   = lane & 3;
    const int mw   = wid >> 2;
    const int nw   = wid & 3;

    float acc[2][4][4];
#pragma unroll
    for (int i = 0; i < 2; i++)
#pragma unroll
        for (int j = 0; j < 4; j++)
#pragma unroll
            for (int k = 0; k < 4; k++) acc[i][j][k] = 0.f;

    const int pr = tid >> 2;
    const int pc = tid & 3;
    const uint32_t p_sts = SWZ((uint32_t)(pr * 64 + pc * 16));
    const int vd = tid & 127;
    const int sg = tid >> 7;
    const uint32_t v_sts = SWZ((uint32_t)(vd * 64 + sg * 16));

    const uint32_t a_row[2] = { (uint32_t)(mw * 32 + 0  + (lane & 15)),
                                (uint32_t)(mw * 32 + 16 + (lane & 15)) };
    const uint32_t a_chq    = (uint32_t)(lane >> 4);
    const uint32_t b_row[2] = { (uint32_t)(nw * 32 + 0  + (lane & 7) + ((lane & 16) >> 1)),
                                (uint32_t)(nw * 32 + 16 + (lane & 7) + ((lane & 16) >> 1)) };
    const uint32_t b_chq    = (uint32_t)((lane >> 3) & 1);

    // ---- prologue: first chunk of this segment -> buffer 0 ----
    {
        float4 pp0 = *(const float4*)(Pb + (size_t)pr * S_ + sc0 + pc * 8);
        float4 pp1 = *(const float4*)(Pb + (size_t)pr * S_ + sc0 + pc * 8 + 4);
        uint4 h, l;
        split8(pp0, pp1, h, l);
        *(uint4*)(sm + p_sts)        = h;
        *(uint4*)(sm + 8192 + p_sts) = l;

        float4 va, vbq;
        va.x  = Vb[(size_t)(sc0 + sg * 8 + 0) * D_ + vd];
        va.y  = Vb[(size_t)(sc0 + sg * 8 + 1) * D_ + vd];
        va.z  = Vb[(size_t)(sc0 + sg * 8 + 2) * D_ + vd];
        va.w  = Vb[(size_t)(sc0 + sg * 8 + 3) * D_ + vd];
        vbq.x = Vb[(size_t)(sc0 + sg * 8 + 4) * D_ + vd];
        vbq.y = Vb[(size_t)(sc0 + sg * 8 + 5) * D_ + vd];
        vbq.z = Vb[(size_t)(sc0 + sg * 8 + 6) * D_ + vd];
        vbq.w = Vb[(size_t)(sc0 + sg * 8 + 7) * D_ + vd];
        split8(va, vbq, h, l);
        *(uint4*)(sm + 16384 + v_sts) = h;
        *(uint4*)(sm + 24576 + v_sts) = l;
    }
    __syncthreads();

    for (int sc = sc0; sc < sc0 + SSEG; sc += 32) {
        const uint32_t cur = ((sc >> 5) & 1) * 32768u;
        const uint32_t nxt = cur ^ 32768u;
        const bool more = (sc + 32 < sc0 + SSEG);

        float4 pp0, pp1, va, vbq;
        if (more) {
            pp0 = *(const float4*)(Pb + (size_t)pr * S_ + sc + 32 + pc * 8);
            pp1 = *(const float4*)(Pb + (size_t)pr * S_ + sc + 32 + pc * 8 + 4);
            va.x  = Vb[(size_t)(sc + 32 + sg * 8 + 0) * D_ + vd];
            va.y  = Vb[(size_t)(sc + 32 + sg * 8 + 1) * D_ + vd];
            va.z  = Vb[(size_t)(sc + 32 + sg * 8 + 2) * D_ + vd];
            va.w  = Vb[(size_t)(sc + 32 + sg * 8 + 3) * D_ + vd];
            vbq.x = Vb[(size_t)(sc + 32 + sg * 8 + 4) * D_ + vd];
            vbq.y = Vb[(size_t)(sc + 32 + sg * 8 + 5) * D_ + vd];
            vbq.z = Vb[(size_t)(sc + 32 + sg * 8 + 6) * D_ + vd];
            vbq.w = Vb[(size_t)(sc + 32 + sg * 8 + 7) * D_ + vd];
        }

#pragma unroll
        for (int ks = 0; ks < 2; ks++) {
            uint32_t ah[2][4], al[2][4];
#pragma unroll
            for (int mi = 0; mi < 2; mi++) {
                uint32_t off = cur + SWZ(a_row[mi] * 64 + (2 * ks + a_chq) * 16);
                ldsm_x4(ah[mi], sptr(sm) + off);
                ldsm_x4(al[mi], sptr(sm) + 8192 + off);
            }
            uint32_t bh[2][4], bl[2][4];
#pragma unroll
            for (int njp = 0; njp < 2; njp++) {
                uint32_t off = cur + SWZ(b_row[njp] * 64 + (2 * ks + b_chq) * 16);
                ldsm_x4(bh[njp], sptr(sm) + 16384 + off);
                ldsm_x4(bl[njp], sptr(sm) + 24576 + off);
            }
#pragma unroll
            for (int mi = 0; mi < 2; mi++)
#pragma unroll
                for (int njp = 0; njp < 2; njp++)
#pragma unroll
                    for (int j = 0; j < 2; j++) {
                        float (&cacc)[4] = acc[mi][njp * 2 + j];
                        mma16816(cacc, ah[mi], &bh[njp][2 * j]);
                        mma16816(cacc, ah[mi], &bl[njp][2 * j]);
                        mma16816(cacc, al[mi], &bh[njp][2 * j]);
                    }
        }

        if (more) {
            uint4 h, l;
            split8(pp0, pp1, h, l);
            *(uint4*)(sm + nxt + p_sts)        = h;
            *(uint4*)(sm + nxt + 8192 + p_sts) = l;
            split8(va, vbq, h, l);
            *(uint4*)(sm + nxt + 16384 + v_sts) = h;
            *(uint4*)(sm + nxt + 24576 + v_sts) = l;
        }
        __syncthreads();
    }

    // REDG accumulation of partial results
#pragma unroll
    for (int mi = 0; mi < 2; mi++) {
#pragma unroll
        for (int hh = 0; hh < 2; hh++) {
            const int q = q0 + mw * 32 + mi * 16 + hh * 8 + g;
            float* orow = O + ((size_t)b * Q_ + q) * D_;
#pragma unroll
            for (int nj = 0; nj < 4; nj++) {
                const int d = nw * 32 + nj * 8 + tg * 2;
                atomicAdd(orow + d,     acc[mi][nj][hh * 2]);
                atomicAdd(orow + d + 1, acc[mi][nj][hh * 2 + 1]);
            }
        }
    }
}

// ---------------------------------------------------------------------------
extern "C" void kernel_launch(void* const* d_in, const int* in_sizes, int n_in,
                              void* d_out, int out_size)
{
    const size_t MASK_N = (size_t)B_ * Q_ * S_;
    const void* mask = nullptr;
    const float* vkq[3] = {nullptr, nullptr, nullptr};
    int nv = 0;
    for (int i = 0; i < n_in; i++) {
        if ((size_t)in_sizes[i] == MASK_N && mask == nullptr) {
            mask = d_in[i];
        } else if (nv < 3) {
            vkq[nv++] = (const float*)d_in[i];
        }
    }
    const float* value = vkq[0];
    const float* key   = vkq[1];
    const float* query = vkq[2];

    float* out  = (float*)d_out;
    float* attn = out + (size_t)B_ * Q_ * D_;

    static bool attr_done = false;
    if (!attr_done) {
        cudaFuncSetAttribute(k_scores, cudaFuncAttributeMaxDynamicSharedMemorySize, 65536);
        cudaFuncSetAttribute(k_pv,     cudaFuncAttributeMaxDynamicSharedMemorySize, 65536);
        attr_done = true;
    }

    k_probe_mask<<<1, 32>>>((const unsigned int*)mask);

    // zero O (k_pv accumulates with atomics); independent of the GEMM chain
    k_zero_out<<<(B_ * Q_ * D_) / 1024, 256>>>((float4*)out);

    dim3 g1(S_ / 128, Q_ / 128, B_);
    k_scores<<<g1, 512, 65536>>>(query, key, mask, attn);

    k_softmax<<<B_ * Q_, 256>>>(attn);

    dim3 g3(Q_ / 128, B_, SSPLIT);
    k_pv<<<g3, 512, 65536>>>(attn, value, out);
}

// round 12
// speedup vs baseline: 1.0530x; 1.0530x over previous
#include <cuda_runtime.h>
#include <cuda_bf16.h>
#include <cstdint>

#define B_ 16
#define Q_ 2048
#define S_ 2048
#define D_ 128
#define NEG_INF __int_as_float(0xff800000)

// byte-level SW128 swizzle (R4-verified)
#define SWZ(o) ((o) ^ (((o) >> 3) & 0x70))

// per-buffer smem layouts (bytes)
#define SC_QH 0
#define SC_QL 8192
#define SC_KH 16384
#define SC_KL 20480
#define SC_BUF 24576

#define PV_PH 0
#define PV_PL 4096
#define PV_VH 8192
#define PV_VL 16384
#define PV_BUF 24576

__device__ int g_mask_mode;   // 0 = uint8, 1 = int32, 2 = float32

// ---------------------------------------------------------------------------
__global__ void k_probe_mask(const unsigned int* __restrict__ m)
{
    const int lane = threadIdx.x;
    bool i32 = true, f32 = true;
    for (int i = lane; i < 1024; i += 32) {
        unsigned int w = m[i];
        if (w > 1u) i32 = false;
        if (w != 0u && w != 0x3F800000u) f32 = false;
    }
    unsigned bi = __ballot_sync(0xffffffffu, i32);
    unsigned bf = __ballot_sync(0xffffffffu, f32);
    if (lane == 0) g_mask_mode = (bi == 0xffffffffu) ? 1 : ((bf == 0xffffffffu) ? 2 : 0);
}

// ---------------------------------------------------------------------------
__device__ __forceinline__ void split_pack(float x, float y, uint32_t& hi, uint32_t& lo)
{
    __nv_bfloat16 hx = __float2bfloat16_rn(x);
    __nv_bfloat16 hy = __float2bfloat16_rn(y);
    __nv_bfloat16 lx = __float2bfloat16_rn(x - __bfloat162float(hx));
    __nv_bfloat16 ly = __float2bfloat16_rn(y - __bfloat162float(hy));
    hi = (uint32_t)__bfloat16_as_ushort(hx) | ((uint32_t)__bfloat16_as_ushort(hy) << 16);
    lo = (uint32_t)__bfloat16_as_ushort(lx) | ((uint32_t)__bfloat16_as_ushort(ly) << 16);
}

__device__ __forceinline__ void split8(const float4& a, const float4& b, uint4& hi, uint4& lo)
{
    split_pack(a.x, a.y, hi.x, lo.x);
    split_pack(a.z, a.w, hi.y, lo.y);
    split_pack(b.x, b.y, hi.z, lo.z);
    split_pack(b.z, b.w, hi.w, lo.w);
}

__device__ __forceinline__ void mma16816(float (&c)[4], const uint32_t (&a)[4], const uint32_t* b)
{
    asm volatile(
        "mma.sync.aligned.m16n8k16.row.col.f32.bf16.bf16.f32 "
        "{%0,%1,%2,%3}, {%4,%5,%6,%7}, {%8,%9}, {%0,%1,%2,%3};\n"
        : "+f"(c[0]), "+f"(c[1]), "+f"(c[2]), "+f"(c[3])
        : "r"(a[0]), "r"(a[1]), "r"(a[2]), "r"(a[3]), "r"(b[0]), "r"(b[1]));
}

__device__ __forceinline__ void ldsm_x4(uint32_t (&r)[4], uint32_t addr)
{
    asm volatile("ldmatrix.sync.aligned.m8n8.x4.shared.b16 {%0,%1,%2,%3}, [%4];\n"
                 : "=r"(r[0]), "=r"(r[1]), "=r"(r[2]), "=r"(r[3]) : "r"(addr));
}

__device__ __forceinline__ uint32_t sptr(const void* p)
{
    return (uint32_t)__cvta_generic_to_shared(p);
}

// ---------------------------------------------------------------------------
// Kernel 1: scores = mask ? -inf : (Q K^T) * D^-0.5
// CTA 128q x 64s, 256 thr (8 warps: 4 mw x 2 nw, warp tile 32x32),
// D chunks of 32, double-buffered (2 x 24KB), 2 CTAs/SM.
// ---------------------------------------------------------------------------
__global__ __launch_bounds__(256, 2) void k_scores(
    const float* __restrict__ Qm, const float* __restrict__ Km,
    const void* __restrict__ mask, float* __restrict__ P)
{
    extern __shared__ __align__(128) uint8_t sm[];

    const int b  = blockIdx.z;
    const int q0 = blockIdx.y * 128;
    const int s0 = blockIdx.x * 64;
    const float* Qb = Qm + ((size_t)b * Q_ + q0) * D_;
    const float* Kb = Km + ((size_t)b * S_ + s0) * D_;

    const int tid  = threadIdx.x;
    const int lane = tid & 31;
    const int wid  = tid >> 5;
    const int g    = lane >> 2;
    const int tg   = lane & 3;
    const int mw   = wid >> 1;     // 0..3 (q)
    const int nw   = wid & 1;      // 0..1 (s)

    float acc[2][4][4];
#pragma unroll
    for (int i = 0; i < 2; i++)
#pragma unroll
        for (int j = 0; j < 4; j++)
#pragma unroll
            for (int k = 0; k < 4; k++) acc[i][j][k] = 0.f;

    // Q conversion: r = tid>>1 (0..127), half-row c = tid&1 (16 floats)
    const int qr = tid >> 1;
    const int qc = tid & 1;
    const uint32_t q_sts0 = SWZ((uint32_t)(qr * 64 + qc * 32));
    const uint32_t q_sts1 = SWZ((uint32_t)(qr * 64 + qc * 32 + 16));
    // K conversion: kr = tid>>2 (0..63), kc = tid&3 (8 floats)
    const int kr = tid >> 2;
    const int kc = tid & 3;
    const uint32_t k_sts = SWZ((uint32_t)(kr * 64 + kc * 16));

    const uint32_t a_row[2] = { (uint32_t)(mw * 32 + 0  + (lane & 15)),
                                (uint32_t)(mw * 32 + 16 + (lane & 15)) };
    const uint32_t a_chq    = (uint32_t)(lane >> 4);
    const uint32_t b_row[2] = { (uint32_t)(nw * 32 + 0  + (lane & 7) + ((lane & 16) >> 1)),
                                (uint32_t)(nw * 32 + 16 + (lane & 7) + ((lane & 16) >> 1)) };
    const uint32_t b_chq    = (uint32_t)((lane >> 3) & 1);

    // ---- prologue: chunk 0 -> buffer 0 ----
    {
        const float* qp = Qb + (size_t)qr * D_ + qc * 16;
        float4 q0v = *(const float4*)(qp + 0);
        float4 q1v = *(const float4*)(qp + 4);
        float4 q2v = *(const float4*)(qp + 8);
        float4 q3v = *(const float4*)(qp + 12);
        float4 k0v = *(const float4*)(Kb + (size_t)kr * D_ + kc * 8);
        float4 k1v = *(const float4*)(Kb + (size_t)kr * D_ + kc * 8 + 4);
        uint4 h, l;
        split8(q0v, q1v, h, l);
        *(uint4*)(sm + SC_QH + q_sts0) = h;
        *(uint4*)(sm + SC_QL + q_sts0) = l;
        split8(q2v, q3v, h, l);
        *(uint4*)(sm + SC_QH + q_sts1) = h;
        *(uint4*)(sm + SC_QL + q_sts1) = l;
        split8(k0v, k1v, h, l);
        *(uint4*)(sm + SC_KH + k_sts) = h;
        *(uint4*)(sm + SC_KL + k_sts) = l;
    }
    __syncthreads();

    for (int dc = 0; dc < D_; dc += 32) {
        const uint32_t cur = ((dc >> 5) & 1) * (uint32_t)SC_BUF;
        const uint32_t nxt = cur ^ (uint32_t)SC_BUF;
        const bool more = (dc + 32 < D_);

        float4 q0v, q1v, q2v, q3v, k0v, k1v;
        if (more) {
            const float* qp = Qb + (size_t)qr * D_ + dc + 32 + qc * 16;
            q0v = *(const float4*)(qp + 0);
            q1v = *(const float4*)(qp + 4);
            q2v = *(const float4*)(qp + 8);
            q3v = *(const float4*)(qp + 12);
            k0v = *(const float4*)(Kb + (size_t)kr * D_ + dc + 32 + kc * 8);
            k1v = *(const float4*)(Kb + (size_t)kr * D_ + dc + 32 + kc * 8 + 4);
        }

#pragma unroll
        for (int ks = 0; ks < 2; ks++) {
            uint32_t ah[2][4], al[2][4];
#pragma unroll
            for (int mi = 0; mi < 2; mi++) {
                uint32_t off = cur + SWZ(a_row[mi] * 64 + (2 * ks + a_chq) * 16);
                ldsm_x4(ah[mi], sptr(sm) + SC_QH + off);
                ldsm_x4(al[mi], sptr(sm) + SC_QL + off);
            }
            uint32_t bh[2][4], bl[2][4];
#pragma unroll
            for (int njp = 0; njp < 2; njp++) {
                uint32_t off = cur + SWZ(b_row[njp] * 64 + (2 * ks + b_chq) * 16);
                ldsm_x4(bh[njp], sptr(sm) + SC_KH + off);
                ldsm_x4(bl[njp], sptr(sm) + SC_KL + off);
            }
#pragma unroll
            for (int mi = 0; mi < 2; mi++)
#pragma unroll
                for (int njp = 0; njp < 2; njp++)
#pragma unroll
                    for (int j = 0; j < 2; j++) {
                        float (&cacc)[4] = acc[mi][njp * 2 + j];
                        mma16816(cacc, ah[mi], &bh[njp][2 * j]);
                        mma16816(cacc, ah[mi], &bl[njp][2 * j]);
                        mma16816(cacc, al[mi], &bh[njp][2 * j]);
                    }
        }

        if (more) {
            uint4 h, l;
            split8(q0v, q1v, h, l);
            *(uint4*)(sm + nxt + SC_QH + q_sts0) = h;
            *(uint4*)(sm + nxt + SC_QL + q_sts0) = l;
            split8(q2v, q3v, h, l);
            *(uint4*)(sm + nxt + SC_QH + q_sts1) = h;
            *(uint4*)(sm + nxt + SC_QL + q_sts1) = l;
            split8(k0v, k1v, h, l);
            *(uint4*)(sm + nxt + SC_KH + k_sts) = h;
            *(uint4*)(sm + nxt + SC_KL + k_sts) = l;
        }
        __syncthreads();
    }

    const float scale = 0.08838834764831845f;  // 128^-0.5
    const int mm = g_mask_mode;
#pragma unroll
    for (int mi = 0; mi < 2; mi++) {
#pragma unroll
        for (int hh = 0; hh < 2; hh++) {
            const int q = q0 + mw * 32 + mi * 16 + hh * 8 + g;
            const size_t rowoff = ((size_t)b * Q_ + q) * (size_t)S_;
#pragma unroll
            for (int nj = 0; nj < 4; nj++) {
                const int s = s0 + nw * 32 + nj * 8 + tg * 2;
                const size_t off = rowoff + s;
                const float v0 = acc[mi][nj][hh * 2 + 0] * scale;
                const float v1 = acc[mi][nj][hh * 2 + 1] * scale;
                bool m0, m1;
                if (mm == 1) {
                    int2 w = *(const int2*)((const int*)mask + off);
                    m0 = w.x != 0; m1 = w.y != 0;
                } else if (mm == 2) {
                    float2 w = *(const float2*)((const float*)mask + off);
                    m0 = w.x != 0.f; m1 = w.y != 0.f;
                } else {
                    const unsigned char* mu = (const unsigned char*)mask + off;
                    m0 = mu[0] != 0; m1 = mu[1] != 0;
                }
                float2 o;
                o.x = m0 ? NEG_INF : v0;
                o.y = m1 ? NEG_INF : v1;
                *(float2*)(P + off) = o;
            }
        }
    }
}

// ---------------------------------------------------------------------------
// Kernel 2: in-place row softmax over S=2048. R8-proven, unchanged.
// ---------------------------------------------------------------------------
__global__ __launch_bounds__(256) void k_softmax(float* __restrict__ P)
{
    __shared__ float red[8];
    const size_t row = blockIdx.x;
    float* p = P + row * (size_t)S_;
    const int tid  = threadIdx.x;
    const int lane = tid & 31;
    const int wid  = tid >> 5;

    float4 v0 = ((const float4*)p)[tid];
    float4 v1 = ((const float4*)p)[tid + 256];

    float m = fmaxf(fmaxf(fmaxf(v0.x, v0.y), fmaxf(v0.z, v0.w)),
                    fmaxf(fmaxf(v1.x, v1.y), fmaxf(v1.z, v1.w)));
#pragma unroll
    for (int o = 16; o; o >>= 1) m = fmaxf(m, __shfl_xor_sync(0xffffffffu, m, o));
    if (lane == 0) red[wid] = m;
    __syncthreads();
    m = red[0];
#pragma unroll
    for (int w = 1; w < 8; w++) m = fmaxf(m, red[w]);
    __syncthreads();

    float e[8];
    e[0] = __expf(v0.x - m); e[1] = __expf(v0.y - m);
    e[2] = __expf(v0.z - m); e[3] = __expf(v0.w - m);
    e[4] = __expf(v1.x - m); e[5] = __expf(v1.y - m);
    e[6] = __expf(v1.z - m); e[7] = __expf(v1.w - m);
    float s = ((e[0] + e[1]) + (e[2] + e[3])) + ((e[4] + e[5]) + (e[6] + e[7]));
#pragma unroll
    for (int o = 16; o; o >>= 1) s += __shfl_xor_sync(0xffffffffu, s, o);
    if (lane == 0) red[wid] = s;
    __syncthreads();
    s = red[0];
#pragma unroll
    for (int w = 1; w < 8; w++) s += red[w];

    const float inv = 1.0f / s;
    v0.x = e[0] * inv; v0.y = e[1] * inv; v0.z = e[2] * inv; v0.w = e[3] * inv;
    v1.x = e[4] * inv; v1.y = e[5] * inv; v1.z = e[6] * inv; v1.w = e[7] * inv;
    ((float4*)p)[tid]       = v0;
    ((float4*)p)[tid + 256] = v1;
}

// ---------------------------------------------------------------------------
// Kernel 3: out = P @ V.  CTA 64q x 128d, 256 thr (8 warps: 2 mw x 4 nw,
// warp tile 32x32), S chunks of 32, double-buffered (2 x 24KB), 2 CTAs/SM.
// ---------------------------------------------------------------------------
__global__ __launch_bounds__(256, 2) void k_pv(
    const float* __restrict__ P, const float* __restrict__ V,
    float* __restrict__ O)
{
    extern __shared__ __align__(128) uint8_t sm[];

    const int b  = blockIdx.y;
    const int q0 = blockIdx.x * 64;
    const float* Pb = P + ((size_t)b * Q_ + q0) * (size_t)S_;
    const float* Vb = V + (size_t)b * S_ * D_;

    const int tid  = threadIdx.x;
    const int lane = tid & 31;
    const int wid  = tid >> 5;
    const int g    = lane >> 2;
    const int tg   = lane & 3;
    const int mw   = wid >> 2;    // 0..1 (q)
    const int nw   = wid & 3;     // 0..3 (d)

    float acc[2][4][4];
#pragma unroll
    for (int i = 0; i < 2; i++)
#pragma unroll
        for (int j = 0; j < 4; j++)
#pragma unroll
            for (int k = 0; k < 4; k++) acc[i][j][k] = 0.f;

    // P conversion: pr = tid>>2 (0..63), pc = tid&3 (8 floats)
    const int pr = tid >> 2;
    const int pc = tid & 3;
    const uint32_t p_sts = SWZ((uint32_t)(pr * 64 + pc * 16));
    // V conversion: vd = tid&127 (d-row), sg = tid>>7 (0..1), 16 floats
    const int vd = tid & 127;
    const int sg = tid >> 7;
    const uint32_t v_sts0 = SWZ((uint32_t)(vd * 64 + sg * 32));
    const uint32_t v_sts1 = SWZ((uint32_t)(vd * 64 + sg * 32 + 16));

    const uint32_t a_row[2] = { (uint32_t)(mw * 32 + 0  + (lane & 15)),
                                (uint32_t)(mw * 32 + 16 + (lane & 15)) };
    const uint32_t a_chq    = (uint32_t)(lane >> 4);
    const uint32_t b_row[2] = { (uint32_t)(nw * 32 + 0  + (lane & 7) + ((lane & 16) >> 1)),
                                (uint32_t)(nw * 32 + 16 + (lane & 7) + ((lane & 16) >> 1)) };
    const uint32_t b_chq    = (uint32_t)((lane >> 3) & 1);

    // ---- prologue: chunk 0 -> buffer 0 ----
    {
        float4 pp0 = *(const float4*)(Pb + (size_t)pr * S_ + pc * 8);
        float4 pp1 = *(const float4*)(Pb + (size_t)pr * S_ + pc * 8 + 4);
        uint4 h, l;
        split8(pp0, pp1, h, l);
        *(uint4*)(sm + PV_PH + p_sts) = h;
        *(uint4*)(sm + PV_PL + p_sts) = l;

        float vv[16];
#pragma unroll
        for (int i = 0; i < 16; i++)
            vv[i] = Vb[(size_t)(sg * 16 + i) * D_ + vd];
        float4 a0 = { vv[0],  vv[1],  vv[2],  vv[3]  };
        float4 a1 = { vv[4],  vv[5],  vv[6],  vv[7]  };
        float4 a2 = { vv[8],  vv[9],  vv[10], vv[11] };
        float4 a3 = { vv[12], vv[13], vv[14], vv[15] };
        split8(a0, a1, h, l);
        *(uint4*)(sm + PV_VH + v_sts0) = h;
        *(uint4*)(sm + PV_VL + v_sts0) = l;
        split8(a2, a3, h, l);
        *(uint4*)(sm + PV_VH + v_sts1) = h;
        *(uint4*)(sm + PV_VL + v_sts1) = l;
    }
    __syncthreads();

    for (int sc = 0; sc < S_; sc += 32) {
        const uint32_t cur = ((sc >> 5) & 1) * (uint32_t)PV_BUF;
        const uint32_t nxt = cur ^ (uint32_t)PV_BUF;
        const bool more = (sc + 32 < S_);

        float4 pp0, pp1;
        float vv[16];
        if (more) {
            pp0 = *(const float4*)(Pb + (size_t)pr * S_ + sc + 32 + pc * 8);
            pp1 = *(const float4*)(Pb + (size_t)pr * S_ + sc + 32 + pc * 8 + 4);
#pragma unroll
            for (int i = 0; i < 16; i++)
                vv[i] = Vb[(size_t)(sc + 32 + sg * 16 + i) * D_ + vd];
        }

#pragma unroll
        for (int ks = 0; ks < 2; ks++) {
            uint32_t ah[2][4], al[2][4];
#pragma unroll
            for (int mi = 0; mi < 2; mi++) {
                uint32_t off = cur + SWZ(a_row[mi] * 64 + (2 * ks + a_chq) * 16);
                ldsm_x4(ah[mi], sptr(sm) + PV_PH + off);
                ldsm_x4(al[mi], sptr(sm) + PV_PL + off);
            }
            uint32_t bh[2][4], bl[2][4];
#pragma unroll
            for (int njp = 0; njp < 2; njp++) {
                uint32_t off = cur + SWZ(b_row[njp] * 64 + (2 * ks + b_chq) * 16);
                ldsm_x4(bh[njp], sptr(sm) + PV_VH + off);
                ldsm_x4(bl[njp], sptr(sm) + PV_VL + off);
            }
#pragma unroll
            for (int mi = 0; mi < 2; mi++)
#pragma unroll
                for (int njp = 0; njp < 2; njp++)
#pragma unroll
                    for (int j = 0; j < 2; j++) {
                        float (&cacc)[4] = acc[mi][njp * 2 + j];
                        mma16816(cacc, ah[mi], &bh[njp][2 * j]);
                        mma16816(cacc, ah[mi], &bl[njp][2 * j]);
                        mma16816(cacc, al[mi], &bh[njp][2 * j]);
                    }
        }

        if (more) {
            uint4 h, l;
            split8(pp0, pp1, h, l);
            *(uint4*)(sm + nxt + PV_PH + p_sts) = h;
            *(uint4*)(sm + nxt + PV_PL + p_sts) = l;
            float4 a0 = { vv[0],  vv[1],  vv[2],  vv[3]  };
            float4 a1 = { vv[4],  vv[5],  vv[6],  vv[7]  };
            float4 a2 = { vv[8],  vv[9],  vv[10], vv[11] };
            float4 a3 = { vv[12], vv[13], vv[14], vv[15] };
            split8(a0, a1, h, l);
            *(uint4*)(sm + nxt + PV_VH + v_sts0) = h;
            *(uint4*)(sm + nxt + PV_VL + v_sts0) = l;
            split8(a2, a3, h, l);
            *(uint4*)(sm + nxt + PV_VH + v_sts1) = h;
            *(uint4*)(sm + nxt + PV_VL + v_sts1) = l;
        }
        __syncthreads();
    }

#pragma unroll
    for (int mi = 0; mi < 2; mi++) {
#pragma unroll
        for (int hh = 0; hh < 2; hh++) {
            const int q = q0 + mw * 32 + mi * 16 + hh * 8 + g;
            float* orow = O + ((size_t)b * Q_ + q) * D_;
#pragma unroll
            for (int nj = 0; nj < 4; nj++) {
                const int d = nw * 32 + nj * 8 + tg * 2;
                float2 o = { acc[mi][nj][hh * 2], acc[mi][nj][hh * 2 + 1] };
                *(float2*)(orow + d) = o;
            }
        }
    }
}

// ---------------------------------------------------------------------------
extern "C" void kernel_launch(void* const* d_in, const int* in_sizes, int n_in,
                              void* d_out, int out_size)
{
    const size_t MASK_N = (size_t)B_ * Q_ * S_;
    const void* mask = nullptr;
    const float* vkq[3] = {nullptr, nullptr, nullptr};
    int nv = 0;
    for (int i = 0; i < n_in; i++) {
        if ((size_t)in_sizes[i] == MASK_N && mask == nullptr) {
            mask = d_in[i];
        } else if (nv < 3) {
            vkq[nv++] = (const float*)d_in[i];
        }
    }
    const float* value = vkq[0];
    const float* key   = vkq[1];
    const float* query = vkq[2];

    float* out  = (float*)d_out;
    float* attn = out + (size_t)B_ * Q_ * D_;

    static bool attr_done = false;
    if (!attr_done) {
        cudaFuncSetAttribute(k_scores, cudaFuncAttributeMaxDynamicSharedMemorySize, 2 * SC_BUF);
        cudaFuncSetAttribute(k_pv,     cudaFuncAttributeMaxDynamicSharedMemorySize, 2 * PV_BUF);
        attr_done = true;
    }

    k_probe_mask<<<1, 32>>>((const unsigned int*)mask);

    dim3 g1(S_ / 64, Q_ / 128, B_);
    k_scores<<<g1, 256, 2 * SC_BUF>>>(query, key, mask, attn);

    k_softmax<<<B_ * Q_, 256>>>(attn);

    dim3 g3(Q_ / 64, B_);
    k_pv<<<g3, 256, 2 * PV_BUF>>>(attn, value, out);
}

// round 13
// speedup vs baseline: 1.0625x; 1.0090x over previous
#include <cuda_runtime.h>
#include <cuda_bf16.h>
#include <cstdint>

#define B_ 16
#define Q_ 2048
#define S_ 2048
#define D_ 128
#define NEG_INF __int_as_float(0xff800000)

// byte-level SW128 swizzle (R4-verified)
#define SWZ(o) ((o) ^ (((o) >> 3) & 0x70))

// k_pv per-buffer smem layout (bytes)
#define PV_PH 0
#define PV_PL 4096
#define PV_VH 8192
#define PV_VL 16384
#define PV_BUF 24576

__device__ int g_mask_mode;   // 0 = uint8, 1 = int32, 2 = float32

// ---------------------------------------------------------------------------
__global__ void k_probe_mask(const unsigned int* __restrict__ m)
{
    const int lane = threadIdx.x;
    bool i32 = true, f32 = true;
    for (int i = lane; i < 1024; i += 32) {
        unsigned int w = m[i];
        if (w > 1u) i32 = false;
        if (w != 0u && w != 0x3F800000u) f32 = false;
    }
    unsigned bi = __ballot_sync(0xffffffffu, i32);
    unsigned bf = __ballot_sync(0xffffffffu, f32);
    if (lane == 0) g_mask_mode = (bi == 0xffffffffu) ? 1 : ((bf == 0xffffffffu) ? 2 : 0);
}

// ---------------------------------------------------------------------------
__device__ __forceinline__ void split_pack(float x, float y, uint32_t& hi, uint32_t& lo)
{
    __nv_bfloat16 hx = __float2bfloat16_rn(x);
    __nv_bfloat16 hy = __float2bfloat16_rn(y);
    __nv_bfloat16 lx = __float2bfloat16_rn(x - __bfloat162float(hx));
    __nv_bfloat16 ly = __float2bfloat16_rn(y - __bfloat162float(hy));
    hi = (uint32_t)__bfloat16_as_ushort(hx) | ((uint32_t)__bfloat16_as_ushort(hy) << 16);
    lo = (uint32_t)__bfloat16_as_ushort(lx) | ((uint32_t)__bfloat16_as_ushort(ly) << 16);
}

__device__ __forceinline__ void split8(const float4& a, const float4& b, uint4& hi, uint4& lo)
{
    split_pack(a.x, a.y, hi.x, lo.x);
    split_pack(a.z, a.w, hi.y, lo.y);
    split_pack(b.x, b.y, hi.z, lo.z);
    split_pack(b.z, b.w, hi.w, lo.w);
}

__device__ __forceinline__ void mma16816(float (&c)[4], const uint32_t (&a)[4], const uint32_t* b)
{
    asm volatile(
        "mma.sync.aligned.m16n8k16.row.col.f32.bf16.bf16.f32 "
        "{%0,%1,%2,%3}, {%4,%5,%6,%7}, {%8,%9}, {%0,%1,%2,%3};\n"
        : "+f"(c[0]), "+f"(c[1]), "+f"(c[2]), "+f"(c[3])
        : "r"(a[0]), "r"(a[1]), "r"(a[2]), "r"(a[3]), "r"(b[0]), "r"(b[1]));
}

__device__ __forceinline__ void ldsm_x4(uint32_t (&r)[4], uint32_t addr)
{
    asm volatile("ldmatrix.sync.aligned.m8n8.x4.shared.b16 {%0,%1,%2,%3}, [%4];\n"
                 : "=r"(r[0]), "=r"(r[1]), "=r"(r[2]), "=r"(r[3]) : "r"(addr));
}

__device__ __forceinline__ uint32_t sptr(const void* p)
{
    return (uint32_t)__cvta_generic_to_shared(p);
}

// ---------------------------------------------------------------------------
// Kernel 1: scores = mask ? -inf : (Q K^T) * D^-0.5  -- R8-proven version.
// CTA 128q x 128s, 512 thr (16 warps 4x4, warp tile 32x32), D chunks of 32,
// double-buffered dynamic smem (2 x 32KB).
// ---------------------------------------------------------------------------
__global__ __launch_bounds__(512, 1) void k_scores(
    const float* __restrict__ Qm, const float* __restrict__ Km,
    const void* __restrict__ mask, float* __restrict__ P)
{
    extern __shared__ __align__(128) uint8_t sm[];
    // per buffer: Qh:+0  Ql:+8192  Kh:+16384  Kl:+24576 ; buffers at 0 / 32768

    const int b  = blockIdx.z;
    const int q0 = blockIdx.y * 128;
    const int s0 = blockIdx.x * 128;
    const float* Qb = Qm + ((size_t)b * Q_ + q0) * D_;
    const float* Kb = Km + ((size_t)b * S_ + s0) * D_;

    const int tid  = threadIdx.x;
    const int lane = tid & 31;
    const int wid  = tid >> 5;
    const int g    = lane >> 2;
    const int tg   = lane & 3;
    const int mw   = wid >> 2;
    const int nw   = wid & 3;

    float acc[2][4][4];
#pragma unroll
    for (int i = 0; i < 2; i++)
#pragma unroll
        for (int j = 0; j < 4; j++)
#pragma unroll
            for (int k = 0; k < 4; k++) acc[i][j][k] = 0.f;

    const int r = tid >> 2;
    const int c = tid & 3;
    const uint32_t sts_off = SWZ((uint32_t)(r * 64 + c * 16));

    const uint32_t a_row[2] = { (uint32_t)(mw * 32 + 0  + (lane & 15)),
                                (uint32_t)(mw * 32 + 16 + (lane & 15)) };
    const uint32_t a_chq    = (uint32_t)(lane >> 4);
    const uint32_t b_row[2] = { (uint32_t)(nw * 32 + 0  + (lane & 7) + ((lane & 16) >> 1)),
                                (uint32_t)(nw * 32 + 16 + (lane & 7) + ((lane & 16) >> 1)) };
    const uint32_t b_chq    = (uint32_t)((lane >> 3) & 1);

    // ---- prologue: chunk 0 -> buffer 0 ----
    {
        float4 q0v = *(const float4*)(Qb + (size_t)r * D_ + c * 8);
        float4 q1v = *(const float4*)(Qb + (size_t)r * D_ + c * 8 + 4);
        float4 k0v = *(const float4*)(Kb + (size_t)r * D_ + c * 8);
        float4 k1v = *(const float4*)(Kb + (size_t)r * D_ + c * 8 + 4);
        uint4 h, l;
        split8(q0v, q1v, h, l);
        *(uint4*)(sm + sts_off)        = h;
        *(uint4*)(sm + 8192 + sts_off) = l;
        split8(k0v, k1v, h, l);
        *(uint4*)(sm + 16384 + sts_off) = h;
        *(uint4*)(sm + 24576 + sts_off) = l;
    }
    __syncthreads();

    for (int dc = 0; dc < D_; dc += 32) {
        const uint32_t cur = ((dc >> 5) & 1) * 32768u;
        const uint32_t nxt = cur ^ 32768u;
        const bool more = (dc + 32 < D_);

        float4 q0v, q1v, k0v, k1v;
        if (more) {
            q0v = *(const float4*)(Qb + (size_t)r * D_ + dc + 32 + c * 8);
            q1v = *(const float4*)(Qb + (size_t)r * D_ + dc + 32 + c * 8 + 4);
            k0v = *(const float4*)(Kb + (size_t)r * D_ + dc + 32 + c * 8);
            k1v = *(const float4*)(Kb + (size_t)r * D_ + dc + 32 + c * 8 + 4);
        }

#pragma unroll
        for (int ks = 0; ks < 2; ks++) {
            uint32_t ah[2][4], al[2][4];
#pragma unroll
            for (int mi = 0; mi < 2; mi++) {
                uint32_t off = cur + SWZ(a_row[mi] * 64 + (2 * ks + a_chq) * 16);
                ldsm_x4(ah[mi], sptr(sm) + off);
                ldsm_x4(al[mi], sptr(sm) + 8192 + off);
            }
            uint32_t bh[2][4], bl[2][4];
#pragma unroll
            for (int njp = 0; njp < 2; njp++) {
                uint32_t off = cur + SWZ(b_row[njp] * 64 + (2 * ks + b_chq) * 16);
                ldsm_x4(bh[njp], sptr(sm) + 16384 + off);
                ldsm_x4(bl[njp], sptr(sm) + 24576 + off);
            }
#pragma unroll
            for (int mi = 0; mi < 2; mi++)
#pragma unroll
                for (int njp = 0; njp < 2; njp++)
#pragma unroll
                    for (int j = 0; j < 2; j++) {
                        float (&cacc)[4] = acc[mi][njp * 2 + j];
                        mma16816(cacc, ah[mi], &bh[njp][2 * j]);
                        mma16816(cacc, ah[mi], &bl[njp][2 * j]);
                        mma16816(cacc, al[mi], &bh[njp][2 * j]);
                    }
        }

        if (more) {
            uint4 h, l;
            split8(q0v, q1v, h, l);
            *(uint4*)(sm + nxt + sts_off)        = h;
            *(uint4*)(sm + nxt + 8192 + sts_off) = l;
            split8(k0v, k1v, h, l);
            *(uint4*)(sm + nxt + 16384 + sts_off) = h;
            *(uint4*)(sm + nxt + 24576 + sts_off) = l;
        }
        __syncthreads();
    }

    const float scale = 0.08838834764831845f;  // 128^-0.5
    const int mm = g_mask_mode;
#pragma unroll
    for (int mi = 0; mi < 2; mi++) {
#pragma unroll
        for (int hh = 0; hh < 2; hh++) {
            const int q = q0 + mw * 32 + mi * 16 + hh * 8 + g;
            const size_t rowoff = ((size_t)b * Q_ + q) * (size_t)S_;
#pragma unroll
            for (int nj = 0; nj < 4; nj++) {
                const int s = s0 + nw * 32 + nj * 8 + tg * 2;
                const size_t off = rowoff + s;
                const float v0 = acc[mi][nj][hh * 2 + 0] * scale;
                const float v1 = acc[mi][nj][hh * 2 + 1] * scale;
                bool m0, m1;
                if (mm == 1) {
                    int2 w = *(const int2*)((const int*)mask + off);
                    m0 = w.x != 0; m1 = w.y != 0;
                } else if (mm == 2) {
                    float2 w = *(const float2*)((const float*)mask + off);
                    m0 = w.x != 0.f; m1 = w.y != 0.f;
                } else {
                    const unsigned char* mu = (const unsigned char*)mask + off;
                    m0 = mu[0] != 0; m1 = mu[1] != 0;
                }
                float2 o;
                o.x = m0 ? NEG_INF : v0;
                o.y = m1 ? NEG_INF : v1;
                *(float2*)(P + off) = o;
            }
        }
    }
}

// ---------------------------------------------------------------------------
// Kernel 2: in-place row softmax over S=2048. R8-proven, unchanged.
// ---------------------------------------------------------------------------
__global__ __launch_bounds__(256) void k_softmax(float* __restrict__ P)
{
    __shared__ float red[8];
    const size_t row = blockIdx.x;
    float* p = P + row * (size_t)S_;
    const int tid  = threadIdx.x;
    const int lane = tid & 31;
    const int wid  = tid >> 5;

    float4 v0 = ((const float4*)p)[tid];
    float4 v1 = ((const float4*)p)[tid + 256];

    float m = fmaxf(fmaxf(fmaxf(v0.x, v0.y), fmaxf(v0.z, v0.w)),
                    fmaxf(fmaxf(v1.x, v1.y), fmaxf(v1.z, v1.w)));
#pragma unroll
    for (int o = 16; o; o >>= 1) m = fmaxf(m, __shfl_xor_sync(0xffffffffu, m, o));
    if (lane == 0) red[wid] = m;
    __syncthreads();
    m = red[0];
#pragma unroll
    for (int w = 1; w < 8; w++) m = fmaxf(m, red[w]);
    __syncthreads();

    float e[8];
    e[0] = __expf(v0.x - m); e[1] = __expf(v0.y - m);
    e[2] = __expf(v0.z - m); e[3] = __expf(v0.w - m);
    e[4] = __expf(v1.x - m); e[5] = __expf(v1.y - m);
    e[6] = __expf(v1.z - m); e[7] = __expf(v1.w - m);
    float s = ((e[0] + e[1]) + (e[2] + e[3])) + ((e[4] + e[5]) + (e[6] + e[7]));
#pragma unroll
    for (int o = 16; o; o >>= 1) s += __shfl_xor_sync(0xffffffffu, s, o);
    if (lane == 0) red[wid] = s;
    __syncthreads();
    s = red[0];
#pragma unroll
    for (int w = 1; w < 8; w++) s += red[w];

    const float inv = 1.0f / s;
    v0.x = e[0] * inv; v0.y = e[1] * inv; v0.z = e[2] * inv; v0.w = e[3] * inv;
    v1.x = e[4] * inv; v1.y = e[5] * inv; v1.z = e[6] * inv; v1.w = e[7] * inv;
    ((float4*)p)[tid]       = v0;
    ((float4*)p)[tid + 256] = v1;
}

// ---------------------------------------------------------------------------
// Kernel 3: out = P @ V.  R12-proven version: CTA 64q x 128d, 256 thr
// (8 warps: 2 mw x 4 nw, warp tile 32x32), S chunks of 32,
// double-buffered (2 x 24KB), 2 CTAs/SM.
// ---------------------------------------------------------------------------
__global__ __launch_bounds__(256, 2) void k_pv(
    const float* __restrict__ P, const float* __restrict__ V,
    float* __restrict__ O)
{
    extern __shared__ __align__(128) uint8_t sm[];

    const int b  = blockIdx.y;
    const int q0 = blockIdx.x * 64;
    const float* Pb = P + ((size_t)b * Q_ + q0) * (size_t)S_;
    const float* Vb = V + (size_t)b * S_ * D_;

    const int tid  = threadIdx.x;
    const int lane = tid & 31;
    const int wid  = tid >> 5;
    const int g    = lane >> 2;
    const int tg   = lane & 3;
    const int mw   = wid >> 2;    // 0..1 (q)
    const int nw   = wid & 3;     // 0..3 (d)

    float acc[2][4][4];
#pragma unroll
    for (int i = 0; i < 2; i++)
#pragma unroll
        for (int j = 0; j < 4; j++)
#pragma unroll
            for (int k = 0; k < 4; k++) acc[i][j][k] = 0.f;

    const int pr = tid >> 2;
    const int pc = tid & 3;
    const uint32_t p_sts = SWZ((uint32_t)(pr * 64 + pc * 16));
    const int vd = tid & 127;
    const int sg = tid >> 7;
    const uint32_t v_sts0 = SWZ((uint32_t)(vd * 64 + sg * 32));
    const uint32_t v_sts1 = SWZ((uint32_t)(vd * 64 + sg * 32 + 16));

    const uint32_t a_row[2] = { (uint32_t)(mw * 32 + 0  + (lane & 15)),
                                (uint32_t)(mw * 32 + 16 + (lane & 15)) };
    const uint32_t a_chq    = (uint32_t)(lane >> 4);
    const uint32_t b_row[2] = { (uint32_t)(nw * 32 + 0  + (lane & 7) + ((lane & 16) >> 1)),
                                (uint32_t)(nw * 32 + 16 + (lane & 7) + ((lane & 16) >> 1)) };
    const uint32_t b_chq    = (uint32_t)((lane >> 3) & 1);

    // ---- prologue: chunk 0 -> buffer 0 ----
    {
        float4 pp0 = *(const float4*)(Pb + (size_t)pr * S_ + pc * 8);
        float4 pp1 = *(const float4*)(Pb + (size_t)pr * S_ + pc * 8 + 4);
        uint4 h, l;
        split8(pp0, pp1, h, l);
        *(uint4*)(sm + PV_PH + p_sts) = h;
        *(uint4*)(sm + PV_PL + p_sts) = l;

        float vv[16];
#pragma unroll
        for (int i = 0; i < 16; i++)
            vv[i] = Vb[(size_t)(sg * 16 + i) * D_ + vd];
        float4 a0 = { vv[0],  vv[1],  vv[2],  vv[3]  };
        float4 a1 = { vv[4],  vv[5],  vv[6],  vv[7]  };
        float4 a2 = { vv[8],  vv[9],  vv[10], vv[11] };
        float4 a3 = { vv[12], vv[13], vv[14], vv[15] };
        split8(a0, a1, h, l);
        *(uint4*)(sm + PV_VH + v_sts0) = h;
        *(uint4*)(sm + PV_VL + v_sts0) = l;
        split8(a2, a3, h, l);
        *(uint4*)(sm + PV_VH + v_sts1) = h;
        *(uint4*)(sm + PV_VL + v_sts1) = l;
    }
    __syncthreads();

    for (int sc = 0; sc < S_; sc += 32) {
        const uint32_t cur = ((sc >> 5) & 1) * (uint32_t)PV_BUF;
        const uint32_t nxt = cur ^ (uint32_t)PV_BUF;
        const bool more = (sc + 32 < S_);

        float4 pp0, pp1;
        float vv[16];
        if (more) {
            pp0 = *(const float4*)(Pb + (size_t)pr * S_ + sc + 32 + pc * 8);
            pp1 = *(const float4*)(Pb + (size_t)pr * S_ + sc + 32 + pc * 8 + 4);
#pragma unroll
            for (int i = 0; i < 16; i++)
                vv[i] = Vb[(size_t)(sc + 32 + sg * 16 + i) * D_ + vd];
        }

#pragma unroll
        for (int ks = 0; ks < 2; ks++) {
            uint32_t ah[2][4], al[2][4];
#pragma unroll
            for (int mi = 0; mi < 2; mi++) {
                uint32_t off = cur + SWZ(a_row[mi] * 64 + (2 * ks + a_chq) * 16);
                ldsm_x4(ah[mi], sptr(sm) + PV_PH + off);
                ldsm_x4(al[mi], sptr(sm) + PV_PL + off);
            }
            uint32_t bh[2][4], bl[2][4];
#pragma unroll
            for (int njp = 0; njp < 2; njp++) {
                uint32_t off = cur + SWZ(b_row[njp] * 64 + (2 * ks + b_chq) * 16);
                ldsm_x4(bh[njp], sptr(sm) + PV_VH + off);
                ldsm_x4(bl[njp], sptr(sm) + PV_VL + off);
            }
#pragma unroll
            for (int mi = 0; mi < 2; mi++)
#pragma unroll
                for (int njp = 0; njp < 2; njp++)
#pragma unroll
                    for (int j = 0; j < 2; j++) {
                        float (&cacc)[4] = acc[mi][njp * 2 + j];
                        mma16816(cacc, ah[mi], &bh[njp][2 * j]);
                        mma16816(cacc, ah[mi], &bl[njp][2 * j]);
                        mma16816(cacc, al[mi], &bh[njp][2 * j]);
                    }
        }

        if (more) {
            uint4 h, l;
            split8(pp0, pp1, h, l);
            *(uint4*)(sm + nxt + PV_PH + p_sts) = h;
            *(uint4*)(sm + nxt + PV_PL + p_sts) = l;
            float4 a0 = { vv[0],  vv[1],  vv[2],  vv[3]  };
            float4 a1 = { vv[4],  vv[5],  vv[6],  vv[7]  };
            float4 a2 = { vv[8],  vv[9],  vv[10], vv[11] };
            float4 a3 = { vv[12], vv[13], vv[14], vv[15] };
            split8(a0, a1, h, l);
            *(uint4*)(sm + nxt + PV_VH + v_sts0) = h;
            *(uint4*)(sm + nxt + PV_VL + v_sts0) = l;
            split8(a2, a3, h, l);
            *(uint4*)(sm + nxt + PV_VH + v_sts1) = h;
            *(uint4*)(sm + nxt + PV_VL + v_sts1) = l;
        }
        __syncthreads();
    }

#pragma unroll
    for (int mi = 0; mi < 2; mi++) {
#pragma unroll
        for (int hh = 0; hh < 2; hh++) {
            const int q = q0 + mw * 32 + mi * 16 + hh * 8 + g;
            float* orow = O + ((size_t)b * Q_ + q) * D_;
#pragma unroll
            for (int nj = 0; nj < 4; nj++) {
                const int d = nw * 32 + nj * 8 + tg * 2;
                float2 o = { acc[mi][nj][hh * 2], acc[mi][nj][hh * 2 + 1] };
                *(float2*)(orow + d) = o;
            }
        }
    }
}

// ---------------------------------------------------------------------------
extern "C" void kernel_launch(void* const* d_in, const int* in_sizes, int n_in,
                              void* d_out, int out_size)
{
    const size_t MASK_N = (size_t)B_ * Q_ * S_;
    const void* mask = nullptr;
    const float* vkq[3] = {nullptr, nullptr, nullptr};
    int nv = 0;
    for (int i = 0; i < n_in; i++) {
        if ((size_t)in_sizes[i] == MASK_N && mask == nullptr) {
            mask = d_in[i];
        } else if (nv < 3) {
            vkq[nv++] = (const float*)d_in[i];
        }
    }
    const float* value = vkq[0];
    const float* key   = vkq[1];
    const float* query = vkq[2];

    float* out  = (float*)d_out;
    float* attn = out + (size_t)B_ * Q_ * D_;

    static bool attr_done = false;
    if (!attr_done) {
        cudaFuncSetAttribute(k_scores, cudaFuncAttributeMaxDynamicSharedMemorySize, 65536);
        cudaFuncSetAttribute(k_pv,     cudaFuncAttributeMaxDynamicSharedMemorySize, 2 * PV_BUF);
        attr_done = true;
    }

    k_probe_mask<<<1, 32>>>((const unsigned int*)mask);

    dim3 g1(S_ / 128, Q_ / 128, B_);
    k_scores<<<g1, 512, 65536>>>(query, key, mask, attn);

    k_softmax<<<B_ * Q_, 256>>>(attn);

    dim3 g3(Q_ / 64, B_);
    k_pv<<<g3, 256, 2 * PV_BUF>>>(attn, value, out);
}

// round 14
// speedup vs baseline: 1.0780x; 1.0146x over previous
#include <cuda_runtime.h>
#include <cuda_bf16.h>
#include <cstdint>

#define B_ 16
#define Q_ 2048
#define S_ 2048
#define D_ 128
#define NEG_INF __int_as_float(0xff800000)

// byte-level SW128 swizzle (R4-verified)
#define SWZ(o) ((o) ^ (((o) >> 3) & 0x70))

// k_scores smem layout (bytes): Q staged (4 d-chunk regions), K double-buffered
#define SC_QH   0          // 4 regions x 4KB (64q x 32d bf16 hi)
#define SC_QL   16384      // lo
#define SC_K0   32768      // K buffers base
#define SC_KBUF 16384      // per buffer: Kh 8KB + Kl 8KB
#define SC_KH   0
#define SC_KL   8192
#define SC_SMEM 65536

// k_pv per-buffer smem layout (bytes)
#define PV_PH 0
#define PV_PL 4096
#define PV_VH 8192
#define PV_VL 16384
#define PV_BUF 24576

__device__ int g_mask_mode;   // 0 = uint8, 1 = int32, 2 = float32

// ---------------------------------------------------------------------------
__global__ void k_probe_mask(const unsigned int* __restrict__ m)
{
    const int lane = threadIdx.x;
    bool i32 = true, f32 = true;
    for (int i = lane; i < 1024; i += 32) {
        unsigned int w = m[i];
        if (w > 1u) i32 = false;
        if (w != 0u && w != 0x3F800000u) f32 = false;
    }
    unsigned bi = __ballot_sync(0xffffffffu, i32);
    unsigned bf = __ballot_sync(0xffffffffu, f32);
    if (lane == 0) g_mask_mode = (bi == 0xffffffffu) ? 1 : ((bf == 0xffffffffu) ? 2 : 0);
}

// ---------------------------------------------------------------------------
__device__ __forceinline__ void split_pack(float x, float y, uint32_t& hi, uint32_t& lo)
{
    __nv_bfloat16 hx = __float2bfloat16_rn(x);
    __nv_bfloat16 hy = __float2bfloat16_rn(y);
    __nv_bfloat16 lx = __float2bfloat16_rn(x - __bfloat162float(hx));
    __nv_bfloat16 ly = __float2bfloat16_rn(y - __bfloat162float(hy));
    hi = (uint32_t)__bfloat16_as_ushort(hx) | ((uint32_t)__bfloat16_as_ushort(hy) << 16);
    lo = (uint32_t)__bfloat16_as_ushort(lx) | ((uint32_t)__bfloat16_as_ushort(ly) << 16);
}

__device__ __forceinline__ void split8(const float4& a, const float4& b, uint4& hi, uint4& lo)
{
    split_pack(a.x, a.y, hi.x, lo.x);
    split_pack(a.z, a.w, hi.y, lo.y);
    split_pack(b.x, b.y, hi.z, lo.z);
    split_pack(b.z, b.w, hi.w, lo.w);
}

__device__ __forceinline__ void mma16816(float (&c)[4], const uint32_t (&a)[4], const uint32_t* b)
{
    asm volatile(
        "mma.sync.aligned.m16n8k16.row.col.f32.bf16.bf16.f32 "
        "{%0,%1,%2,%3}, {%4,%5,%6,%7}, {%8,%9}, {%0,%1,%2,%3};\n"
        : "+f"(c[0]), "+f"(c[1]), "+f"(c[2]), "+f"(c[3])
        : "r"(a[0]), "r"(a[1]), "r"(a[2]), "r"(a[3]), "r"(b[0]), "r"(b[1]));
}

__device__ __forceinline__ void ldsm_x4(uint32_t (&r)[4], uint32_t addr)
{
    asm volatile("ldmatrix.sync.aligned.m8n8.x4.shared.b16 {%0,%1,%2,%3}, [%4];\n"
                 : "=r"(r[0]), "=r"(r[1]), "=r"(r[2]), "=r"(r[3]) : "r"(addr));
}

__device__ __forceinline__ uint32_t sptr(const void* p)
{
    return (uint32_t)__cvta_generic_to_shared(p);
}

// ---------------------------------------------------------------------------
// Kernel 1: scores = mask ? -inf : (Q K^T) * D^-0.5
// Q-stripe design: CTA = 64q x S(2048). Q staged in smem once (hi/lo, 32KB);
// mainloop = 16 s-tiles x 4 d-chunks = 64 chunk-iterations, K double-buffered.
// 256 thr (8 warps: 2 mw(q) x 4 nw(s), warp tile 32x32), 2 CTAs/SM.
// ---------------------------------------------------------------------------
__global__ __launch_bounds__(256, 2) void k_scores(
    const float* __restrict__ Qm, const float* __restrict__ Km,
    const void* __restrict__ mask, float* __restrict__ P)
{
    extern __shared__ __align__(128) uint8_t sm[];

    const int b  = blockIdx.y;
    const int q0 = blockIdx.x * 64;
    const float* Qb = Qm + ((size_t)b * Q_ + q0) * D_;
    const float* Kb = Km + (size_t)b * S_ * D_;

    const int tid  = threadIdx.x;
    const int lane = tid & 31;
    const int wid  = tid >> 5;
    const int g    = lane >> 2;
    const int tg   = lane & 3;
    const int mw   = wid >> 2;    // 0..1 (q)
    const int nw   = wid & 3;     // 0..3 (s)

    float acc[2][4][4];
#pragma unroll
    for (int i = 0; i < 2; i++)
#pragma unroll
        for (int j = 0; j < 4; j++)
#pragma unroll
            for (int k = 0; k < 4; k++) acc[i][j][k] = 0.f;

    // Q staging: qr = tid>>2 (0..63), qc = tid&3 (8 floats per d-chunk)
    const int qr = tid >> 2;
    const int qc = tid & 3;
    const uint32_t q_sts = SWZ((uint32_t)(qr * 64 + qc * 16));
    // K conversion: kr = tid>>1 (0..127 s-rows), kc = tid&1 (16 floats)
    const int kr = tid >> 1;
    const int kc = tid & 1;
    const uint32_t k_sts0 = SWZ((uint32_t)(kr * 64 + kc * 32));
    const uint32_t k_sts1 = SWZ((uint32_t)(kr * 64 + kc * 32 + 16));

    const uint32_t a_row[2] = { (uint32_t)(mw * 32 + 0  + (lane & 15)),
                                (uint32_t)(mw * 32 + 16 + (lane & 15)) };
    const uint32_t a_chq    = (uint32_t)(lane >> 4);
    const uint32_t b_row[2] = { (uint32_t)(nw * 32 + 0  + (lane & 7) + ((lane & 16) >> 1)),
                                (uint32_t)(nw * 32 + 16 + (lane & 7) + ((lane & 16) >> 1)) };
    const uint32_t b_chq    = (uint32_t)((lane >> 3) & 1);

    // ---- stage Q (all 4 d-chunks, hi/lo) ----
#pragma unroll
    for (int dc = 0; dc < 4; dc++) {
        float4 v0 = *(const float4*)(Qb + (size_t)qr * D_ + dc * 32 + qc * 8);
        float4 v1 = *(const float4*)(Qb + (size_t)qr * D_ + dc * 32 + qc * 8 + 4);
        uint4 h, l;
        split8(v0, v1, h, l);
        *(uint4*)(sm + SC_QH + dc * 4096 + q_sts) = h;
        *(uint4*)(sm + SC_QL + dc * 4096 + q_sts) = l;
    }
    // ---- K chunk 0 (s-tile 0, d-chunk 0) -> buffer 0 ----
    {
        const float* kp = Kb + (size_t)kr * D_ + kc * 16;
        float4 v0 = *(const float4*)(kp + 0);
        float4 v1 = *(const float4*)(kp + 4);
        float4 v2 = *(const float4*)(kp + 8);
        float4 v3 = *(const float4*)(kp + 12);
        uint4 h, l;
        split8(v0, v1, h, l);
        *(uint4*)(sm + SC_K0 + SC_KH + k_sts0) = h;
        *(uint4*)(sm + SC_K0 + SC_KL + k_sts0) = l;
        split8(v2, v3, h, l);
        *(uint4*)(sm + SC_K0 + SC_KH + k_sts1) = h;
        *(uint4*)(sm + SC_K0 + SC_KL + k_sts1) = l;
    }
    __syncthreads();

    const float scale = 0.08838834764831845f;  // 128^-0.5
    const int mm = g_mask_mode;

    for (int it = 0; it < 64; it++) {
        const int st = it >> 2;
        const int dc = it & 3;
        const uint32_t cur = SC_K0 + (uint32_t)(it & 1) * SC_KBUF;
        const bool more = (it + 1 < 64);

        // prefetch next K chunk into registers
        float4 kv0, kv1, kv2, kv3;
        if (more) {
            const int st1 = (it + 1) >> 2;
            const int dc1 = (it + 1) & 3;
            const float* kp = Kb + (size_t)(st1 * 128 + kr) * D_ + dc1 * 32 + kc * 16;
            kv0 = *(const float4*)(kp + 0);
            kv1 = *(const float4*)(kp + 4);
            kv2 = *(const float4*)(kp + 8);
            kv3 = *(const float4*)(kp + 12);
        }

        // MMAs: A from staged Q region dc, B from current K buffer
#pragma unroll
        for (int ks = 0; ks < 2; ks++) {
            uint32_t ah[2][4], al[2][4];
#pragma unroll
            for (int mi = 0; mi < 2; mi++) {
                uint32_t off = SWZ(a_row[mi] * 64 + (2 * ks + a_chq) * 16);
                ldsm_x4(ah[mi], sptr(sm) + SC_QH + dc * 4096 + off);
                ldsm_x4(al[mi], sptr(sm) + SC_QL + dc * 4096 + off);
            }
            uint32_t bh[2][4], bl[2][4];
#pragma unroll
            for (int njp = 0; njp < 2; njp++) {
                uint32_t off = cur + SWZ(b_row[njp] * 64 + (2 * ks + b_chq) * 16);
                ldsm_x4(bh[njp], sptr(sm) + SC_KH + off);
                ldsm_x4(bl[njp], sptr(sm) + SC_KL + off);
            }
#pragma unroll
            for (int mi = 0; mi < 2; mi++)
#pragma unroll
                for (int njp = 0; njp < 2; njp++)
#pragma unroll
                    for (int j = 0; j < 2; j++) {
                        float (&cacc)[4] = acc[mi][njp * 2 + j];
                        mma16816(cacc, ah[mi], &bh[njp][2 * j]);
                        mma16816(cacc, ah[mi], &bl[njp][2 * j]);
                        mma16816(cacc, al[mi], &bh[njp][2 * j]);
                    }
        }

        // end of s-tile: epilogue + reset acc
        if (dc == 3) {
            const int s_base = st * 128;
#pragma unroll
            for (int mi = 0; mi < 2; mi++) {
#pragma unroll
                for (int hh = 0; hh < 2; hh++) {
                    const int q = q0 + mw * 32 + mi * 16 + hh * 8 + g;
                    const size_t rowoff = ((size_t)b * Q_ + q) * (size_t)S_;
#pragma unroll
                    for (int nj = 0; nj < 4; nj++) {
                        const int s = s_base + nw * 32 + nj * 8 + tg * 2;
                        const size_t off = rowoff + s;
                        const float v0 = acc[mi][nj][hh * 2 + 0] * scale;
                        const float v1 = acc[mi][nj][hh * 2 + 1] * scale;
                        bool m0, m1;
                        if (mm == 1) {
                            int2 w = *(const int2*)((const int*)mask + off);
                            m0 = w.x != 0; m1 = w.y != 0;
                        } else if (mm == 2) {
                            float2 w = *(const float2*)((const float*)mask + off);
                            m0 = w.x != 0.f; m1 = w.y != 0.f;
                        } else {
                            const unsigned char* mu = (const unsigned char*)mask + off;
                            m0 = mu[0] != 0; m1 = mu[1] != 0;
                        }
                        float2 o;
                        o.x = m0 ? NEG_INF : v0;
                        o.y = m1 ? NEG_INF : v1;
                        *(float2*)(P + off) = o;
                    }
                }
            }
#pragma unroll
            for (int i = 0; i < 2; i++)
#pragma unroll
                for (int j = 0; j < 4; j++)
#pragma unroll
                    for (int k = 0; k < 4; k++) acc[i][j][k] = 0.f;
        }

        // store prefetched K chunk to the other buffer
        if (more) {
            const uint32_t nb = SC_K0 + (uint32_t)((it + 1) & 1) * SC_KBUF;
            uint4 h, l;
            split8(kv0, kv1, h, l);
            *(uint4*)(sm + nb + SC_KH + k_sts0) = h;
            *(uint4*)(sm + nb + SC_KL + k_sts0) = l;
            split8(kv2, kv3, h, l);
            *(uint4*)(sm + nb + SC_KH + k_sts1) = h;
            *(uint4*)(sm + nb + SC_KL + k_sts1) = l;
        }
        __syncthreads();
    }
}

// ---------------------------------------------------------------------------
// Kernel 2: in-place row softmax over S=2048. R8-proven, unchanged.
// ---------------------------------------------------------------------------
__global__ __launch_bounds__(256) void k_softmax(float* __restrict__ P)
{
    __shared__ float red[8];
    const size_t row = blockIdx.x;
    float* p = P + row * (size_t)S_;
    const int tid  = threadIdx.x;
    const int lane = tid & 31;
    const int wid  = tid >> 5;

    float4 v0 = ((const float4*)p)[tid];
    float4 v1 = ((const float4*)p)[tid + 256];

    float m = fmaxf(fmaxf(fmaxf(v0.x, v0.y), fmaxf(v0.z, v0.w)),
                    fmaxf(fmaxf(v1.x, v1.y), fmaxf(v1.z, v1.w)));
#pragma unroll
    for (int o = 16; o; o >>= 1) m = fmaxf(m, __shfl_xor_sync(0xffffffffu, m, o));
    if (lane == 0) red[wid] = m;
    __syncthreads();
    m = red[0];
#pragma unroll
    for (int w = 1; w < 8; w++) m = fmaxf(m, red[w]);
    __syncthreads();

    float e[8];
    e[0] = __expf(v0.x - m); e[1] = __expf(v0.y - m);
    e[2] = __expf(v0.z - m); e[3] = __expf(v0.w - m);
    e[4] = __expf(v1.x - m); e[5] = __expf(v1.y - m);
    e[6] = __expf(v1.z - m); e[7] = __expf(v1.w - m);
    float s = ((e[0] + e[1]) + (e[2] + e[3])) + ((e[4] + e[5]) + (e[6] + e[7]));
#pragma unroll
    for (int o = 16; o; o >>= 1) s += __shfl_xor_sync(0xffffffffu, s, o);
    if (lane == 0) red[wid] = s;
    __syncthreads();
    s = red[0];
#pragma unroll
    for (int w = 1; w < 8; w++) s += red[w];

    const float inv = 1.0f / s;
    v0.x = e[0] * inv; v0.y = e[1] * inv; v0.z = e[2] * inv; v0.w = e[3] * inv;
    v1.x = e[4] * inv; v1.y = e[5] * inv; v1.z = e[6] * inv; v1.w = e[7] * inv;
    ((float4*)p)[tid]       = v0;
    ((float4*)p)[tid + 256] = v1;
}

// ---------------------------------------------------------------------------
// Kernel 3: out = P @ V.  R12/R13-proven: CTA 64q x 128d, 256 thr
// (8 warps: 2 mw x 4 nw, warp tile 32x32), S chunks of 32,
// double-buffered (2 x 24KB), 2 CTAs/SM.
// ---------------------------------------------------------------------------
__global__ __launch_bounds__(256, 2) void k_pv(
    const float* __restrict__ P, const float* __restrict__ V,
    float* __restrict__ O)
{
    extern __shared__ __align__(128) uint8_t sm[];

    const int b  = blockIdx.y;
    const int q0 = blockIdx.x * 64;
    const float* Pb = P + ((size_t)b * Q_ + q0) * (size_t)S_;
    const float* Vb = V + (size_t)b * S_ * D_;

    const int tid  = threadIdx.x;
    const int lane = tid & 31;
    const int wid  = tid >> 5;
    const int g    = lane >> 2;
    const int tg   = lane & 3;
    const int mw   = wid >> 2;    // 0..1 (q)
    const int nw   = wid & 3;     // 0..3 (d)

    float acc[2][4][4];
#pragma unroll
    for (int i = 0; i < 2; i++)
#pragma unroll
        for (int j = 0; j < 4; j++)
#pragma unroll
            for (int k = 0; k < 4; k++) acc[i][j][k] = 0.f;

    const int pr = tid >> 2;
    const int pc = tid & 3;
    const uint32_t p_sts = SWZ((uint32_t)(pr * 64 + pc * 16));
    const int vd = tid & 127;
    const int sg = tid >> 7;
    const uint32_t v_sts0 = SWZ((uint32_t)(vd * 64 + sg * 32));
    const uint32_t v_sts1 = SWZ((uint32_t)(vd * 64 + sg * 32 + 16));

    const uint32_t a_row[2] = { (uint32_t)(mw * 32 + 0  + (lane & 15)),
                                (uint32_t)(mw * 32 + 16 + (lane & 15)) };
    const uint32_t a_chq    = (uint32_t)(lane >> 4);
    const uint32_t b_row[2] = { (uint32_t)(nw * 32 + 0  + (lane & 7) + ((lane & 16) >> 1)),
                                (uint32_t)(nw * 32 + 16 + (lane & 7) + ((lane & 16) >> 1)) };
    const uint32_t b_chq    = (uint32_t)((lane >> 3) & 1);

    // ---- prologue: chunk 0 -> buffer 0 ----
    {
        float4 pp0 = *(const float4*)(Pb + (size_t)pr * S_ + pc * 8);
        float4 pp1 = *(const float4*)(Pb + (size_t)pr * S_ + pc * 8 + 4);
        uint4 h, l;
        split8(pp0, pp1, h, l);
        *(uint4*)(sm + PV_PH + p_sts) = h;
        *(uint4*)(sm + PV_PL + p_sts) = l;

        float vv[16];
#pragma unroll
        for (int i = 0; i < 16; i++)
            vv[i] = Vb[(size_t)(sg * 16 + i) * D_ + vd];
        float4 a0 = { vv[0],  vv[1],  vv[2],  vv[3]  };
        float4 a1 = { vv[4],  vv[5],  vv[6],  vv[7]  };
        float4 a2 = { vv[8],  vv[9],  vv[10], vv[11] };
        float4 a3 = { vv[12], vv[13], vv[14], vv[15] };
        split8(a0, a1, h, l);
        *(uint4*)(sm + PV_VH + v_sts0) = h;
        *(uint4*)(sm + PV_VL + v_sts0) = l;
        split8(a2, a3, h, l);
        *(uint4*)(sm + PV_VH + v_sts1) = h;
        *(uint4*)(sm + PV_VL + v_sts1) = l;
    }
    __syncthreads();

    for (int sc = 0; sc < S_; sc += 32) {
        const uint32_t cur = ((sc >> 5) & 1) * (uint32_t)PV_BUF;
        const uint32_t nxt = cur ^ (uint32_t)PV_BUF;
        const bool more = (sc + 32 < S_);

        float4 pp0, pp1;
        float vv[16];
        if (more) {
            pp0 = *(const float4*)(Pb + (size_t)pr * S_ + sc + 32 + pc * 8);
            pp1 = *(const float4*)(Pb + (size_t)pr * S_ + sc + 32 + pc * 8 + 4);
#pragma unroll
            for (int i = 0; i < 16; i++)
                vv[i] = Vb[(size_t)(sc + 32 + sg * 16 + i) * D_ + vd];
        }

#pragma unroll
        for (int ks = 0; ks < 2; ks++) {
            uint32_t ah[2][4], al[2][4];
#pragma unroll
            for (int mi = 0; mi < 2; mi++) {
                uint32_t off = cur + SWZ(a_row[mi] * 64 + (2 * ks + a_chq) * 16);
                ldsm_x4(ah[mi], sptr(sm) + PV_PH + off);
                ldsm_x4(al[mi], sptr(sm) + PV_PL + off);
            }
            uint32_t bh[2][4], bl[2][4];
#pragma unroll
            for (int njp = 0; njp < 2; njp++) {
                uint32_t off = cur + SWZ(b_row[njp] * 64 + (2 * ks + b_chq) * 16);
                ldsm_x4(bh[njp], sptr(sm) + PV_VH + off);
                ldsm_x4(bl[njp], sptr(sm) + PV_VL + off);
            }
#pragma unroll
            for (int mi = 0; mi < 2; mi++)
#pragma unroll
                for (int njp = 0; njp < 2; njp++)
#pragma unroll
                    for (int j = 0; j < 2; j++) {
                        float (&cacc)[4] = acc[mi][njp * 2 + j];
                        mma16816(cacc, ah[mi], &bh[njp][2 * j]);
                        mma16816(cacc, ah[mi], &bl[njp][2 * j]);
                        mma16816(cacc, al[mi], &bh[njp][2 * j]);
                    }
        }

        if (more) {
            uint4 h, l;
            split8(pp0, pp1, h, l);
            *(uint4*)(sm + nxt + PV_PH + p_sts) = h;
            *(uint4*)(sm + nxt + PV_PL + p_sts) = l;
            float4 a0 = { vv[0],  vv[1],  vv[2],  vv[3]  };
            float4 a1 = { vv[4],  vv[5],  vv[6],  vv[7]  };
            float4 a2 = { vv[8],  vv[9],  vv[10], vv[11] };
            float4 a3 = { vv[12], vv[13], vv[14], vv[15] };
            split8(a0, a1, h, l);
            *(uint4*)(sm + nxt + PV_VH + v_sts0) = h;
            *(uint4*)(sm + nxt + PV_VL + v_sts0) = l;
            split8(a2, a3, h, l);
            *(uint4*)(sm + nxt + PV_VH + v_sts1) = h;
            *(uint4*)(sm + nxt + PV_VL + v_sts1) = l;
        }
        __syncthreads();
    }

#pragma unroll
    for (int mi = 0; mi < 2; mi++) {
#pragma unroll
        for (int hh = 0; hh < 2; hh++) {
            const int q = q0 + mw * 32 + mi * 16 + hh * 8 + g;
            float* orow = O + ((size_t)b * Q_ + q) * D_;
#pragma unroll
            for (int nj = 0; nj < 4; nj++) {
                const int d = nw * 32 + nj * 8 + tg * 2;
                float2 o = { acc[mi][nj][hh * 2], acc[mi][nj][hh * 2 + 1] };
                *(float2*)(orow + d) = o;
            }
        }
    }
}

// ---------------------------------------------------------------------------
extern "C" void kernel_launch(void* const* d_in, const int* in_sizes, int n_in,
                              void* d_out, int out_size)
{
    const size_t MASK_N = (size_t)B_ * Q_ * S_;
    const void* mask = nullptr;
    const float* vkq[3] = {nullptr, nullptr, nullptr};
    int nv = 0;
    for (int i = 0; i < n_in; i++) {
        if ((size_t)in_sizes[i] == MASK_N && mask == nullptr) {
            mask = d_in[i];
        } else if (nv < 3) {
            vkq[nv++] = (const float*)d_in[i];
        }
    }
    const float* value = vkq[0];
    const float* key   = vkq[1];
    const float* query = vkq[2];

    float* out  = (float*)d_out;
    float* attn = out + (size_t)B_ * Q_ * D_;

    static bool attr_done = false;
    if (!attr_done) {
        cudaFuncSetAttribute(k_scores, cudaFuncAttributeMaxDynamicSharedMemorySize, SC_SMEM);
        cudaFuncSetAttribute(k_pv,     cudaFuncAttributeMaxDynamicSharedMemorySize, 2 * PV_BUF);
        attr_done = true;
    }

    k_probe_mask<<<1, 32>>>((const unsigned int*)mask);

    dim3 g1(Q_ / 64, B_);
    k_scores<<<g1, 256, SC_SMEM>>>(query, key, mask, attn);

    k_softmax<<<B_ * Q_, 256>>>(attn);

    dim3 g3(Q_ / 64, B_);
    k_pv<<<g3, 256, 2 * PV_BUF>>>(attn, value, out);
}